// round 1
// baseline (speedup 1.0000x reference)
#include <cuda_runtime.h>

#define B_    16
#define N_    2048
#define D_    1024
#define KH    15
#define KL    5
#define ROWS  320      // B_*KH + B_*KL
#define HROWS 240      // B_*KH
#define SPLITK 8
#define KC    (D_ / SPLITK)   // 128

// ---------------- scratch (no allocations allowed) ----------------
__device__ unsigned int g_max_bits;
__device__ unsigned int g_min_bits;
__device__ float        g_sum;
__device__ int          g_idx[ROWS];
__device__ int          g_val[ROWS];
__device__ int          g_lab[ROWS];
__device__ __align__(16) float g_bank[ROWS * D_];
__device__ __align__(16) float g_Gk[SPLITK][ROWS * ROWS];
__device__ float        g_per[ROWS];

// ---------------- 0: init accumulators ----------------
__global__ void k_init() {
    g_max_bits = 0u;
    g_min_bits = 0xFFFFFFFFu;
    g_sum = 0.f;
}

// ---------------- 1: global min/max/sum of score ----------------
__global__ void k_reduce(const float* __restrict__ score) {
    __shared__ unsigned int smx[256], smn[256];
    __shared__ float ssum[256];
    int tid = threadIdx.x;
    unsigned int mx = 0u, mn = 0xFFFFFFFFu;
    float s = 0.f;
    int base = blockIdx.x * 1024;
    for (int j = tid; j < 1024; j += 256) {
        float v = score[base + j];
        unsigned int bb = __float_as_uint(v);   // score >= 0 -> bits monotonic
        mx = mx > bb ? mx : bb;
        mn = mn < bb ? mn : bb;
        s += v;
    }
    smx[tid] = mx; smn[tid] = mn; ssum[tid] = s;
    __syncthreads();
    for (int w = 128; w > 0; w >>= 1) {
        if (tid < w) {
            smx[tid] = max(smx[tid], smx[tid + w]);
            smn[tid] = min(smn[tid], smn[tid + w]);
            ssum[tid] += ssum[tid + w];
        }
        __syncthreads();
    }
    if (tid == 0) {
        atomicMax(&g_max_bits, smx[0]);
        atomicMin(&g_min_bits, smn[0]);
        atomicAdd(&g_sum, ssum[0]);
    }
}

// ---------------- 2: per-bag selection ----------------
// key = (float_bits(score) << 32) | index  -> lexicographic (score, idx),
// exactly matching jnp stable ascending argsort semantics.
__global__ void k_select(const float* __restrict__ score,
                         const int* __restrict__ label) {
    __shared__ float s_sc[N_];
    __shared__ unsigned long long s_red[256];
    __shared__ unsigned long long s_sel[10];
    int b = blockIdx.x, tid = threadIdx.x;

    for (int i = tid; i < N_; i += 256) s_sc[i] = score[b * N_ + i];
    float gmax = __uint_as_float(g_max_bits);
    float gmin = __uint_as_float(g_min_bits);
    __syncthreads();

    // ---- HIGH: 15 smallest keys with score in [gmax-0.3, gmax] ----
    {
        float lo = gmax - 0.3f, hi = gmax;
        unsigned long long prevp = 0ULL;
        for (int t = 0; t < KH; t++) {
            unsigned long long m = ~0ULL;
            for (int j = tid; j < N_; j += 256) {
                float s = s_sc[j];
                if (s >= lo && s <= hi) {
                    unsigned long long k =
                        ((unsigned long long)__float_as_uint(s) << 32) | (unsigned)j;
                    if (k >= prevp && k < m) m = k;
                }
            }
            s_red[tid] = m;
            __syncthreads();
            for (int w = 128; w > 0; w >>= 1) {
                if (tid < w) {
                    unsigned long long o = s_red[tid + w];
                    if (o < s_red[tid]) s_red[tid] = o;
                }
                __syncthreads();
            }
            unsigned long long best = s_red[0];
            __syncthreads();
            if (tid == 0) {
                int r = b * KH + t;
                if (best != ~0ULL) {
                    g_val[r] = 1;
                    g_idx[r] = b * N_ + (int)(best & 0xFFFFFFFFULL);
                } else {
                    g_val[r] = 0;
                    g_idx[r] = 0;
                }
                g_lab[r] = label[b];
            }
            prevp = (best == ~0ULL) ? ~0ULL : best + 1ULL;
        }
    }

    // ---- LOW: up to 10 smallest keys with score in [gmin, gmin+1e-9];
    //          keep even ranks 0,2,4,6,8 ----
    {
        float lo = gmin, hi = gmin + 1e-9f;
        unsigned long long prevp = 0ULL;
        for (int t = 0; t < 10; t++) {
            unsigned long long m = ~0ULL;
            for (int j = tid; j < N_; j += 256) {
                float s = s_sc[j];
                if (s >= lo && s <= hi) {
                    unsigned long long k =
                        ((unsigned long long)__float_as_uint(s) << 32) | (unsigned)j;
                    if (k >= prevp && k < m) m = k;
                }
            }
            s_red[tid] = m;
            __syncthreads();
            for (int w = 128; w > 0; w >>= 1) {
                if (tid < w) {
                    unsigned long long o = s_red[tid + w];
                    if (o < s_red[tid]) s_red[tid] = o;
                }
                __syncthreads();
            }
            unsigned long long best = s_red[0];
            __syncthreads();
            if (tid == 0) s_sel[t] = best;
            prevp = (best == ~0ULL) ? ~0ULL : best + 1ULL;
        }
        __syncthreads();
        if (tid == 0) {
            for (int j = 0; j < KL; j++) {
                unsigned long long k = s_sel[2 * j];
                int r = HROWS + b * KL + j;
                if (k != ~0ULL) {
                    g_val[r] = 1;
                    g_idx[r] = b * N_ + (int)(k & 0xFFFFFFFFULL);
                } else {
                    g_val[r] = 0;
                    g_idx[r] = 0;
                }
                g_lab[r] = 2;  // N_CLASSES
            }
        }
    }
}

// ---------------- 3: gather 320 feature rows (zero when invalid) ----------------
__global__ void k_gather(const float* __restrict__ fea) {
    int r = blockIdx.x, tid = threadIdx.x;          // 320 blocks x 256 threads
    float4* dst = (float4*)(g_bank + (size_t)r * D_);
    if (g_val[r]) {
        const float4* src = (const float4*)(fea + (size_t)g_idx[r] * D_);
        dst[tid] = src[tid];
    } else {
        dst[tid] = make_float4(0.f, 0.f, 0.f, 0.f);
    }
}

// ---------------- 4: gram G = X * X^T (320x320, K=1024), split-K into slabs ----------------
#define BM 64
#define BN 64
#define BK 16
__global__ void __launch_bounds__(256) k_gemm() {
    __shared__ float As[BK][BM + 1];
    __shared__ float Bs[BK][BN + 1];
    int bm = blockIdx.x, bn = blockIdx.y, kz = blockIdx.z;
    int tid = threadIdx.x;
    int tx = tid & 15, ty = tid >> 4;

    float c[4][4] = {};

    int loadRow = tid >> 2;           // 0..63
    int loadK4  = (tid & 3) * 4;      // 0,4,8,12
    const float* A0 = g_bank + (size_t)(bm * BM + loadRow) * D_ + kz * KC;
    const float* B0 = g_bank + (size_t)(bn * BN + loadRow) * D_ + kz * KC;

    for (int k0 = 0; k0 < KC; k0 += BK) {
        float4 a  = *(const float4*)(A0 + k0 + loadK4);
        float4 b4 = *(const float4*)(B0 + k0 + loadK4);
        As[loadK4 + 0][loadRow] = a.x;
        As[loadK4 + 1][loadRow] = a.y;
        As[loadK4 + 2][loadRow] = a.z;
        As[loadK4 + 3][loadRow] = a.w;
        Bs[loadK4 + 0][loadRow] = b4.x;
        Bs[loadK4 + 1][loadRow] = b4.y;
        Bs[loadK4 + 2][loadRow] = b4.z;
        Bs[loadK4 + 3][loadRow] = b4.w;
        __syncthreads();
#pragma unroll
        for (int k = 0; k < BK; k++) {
            float ra[4], rb[4];
#pragma unroll
            for (int i = 0; i < 4; i++) ra[i] = As[k][ty * 4 + i];
#pragma unroll
            for (int j = 0; j < 4; j++) rb[j] = Bs[k][tx * 4 + j];
#pragma unroll
            for (int i = 0; i < 4; i++)
#pragma unroll
                for (int j = 0; j < 4; j++) c[i][j] += ra[i] * rb[j];
        }
        __syncthreads();
    }

    float* out = g_Gk[kz];
#pragma unroll
    for (int i = 0; i < 4; i++) {
        int row = bm * BM + ty * 4 + i;
        float4 v = make_float4(c[i][0], c[i][1], c[i][2], c[i][3]);
        *(float4*)(out + (size_t)row * ROWS + bn * BN + tx * 4) = v;
    }
}

// ---------------- 5: per-query num/den + per-row loss ----------------
__global__ void k_rowloss() {
    __shared__ float s_den[128], s_num[128];
    int q = blockIdx.x, tid = threadIdx.x;
    int labq = g_lab[q];
    float den = 0.f, num = 0.f;
    for (int n = tid; n < ROWS; n += 128) {
        float g = 0.f;
#pragma unroll
        for (int s = 0; s < SPLITK; s++) g += g_Gk[s][q * ROWS + n];
        float e = expf(g * (1.0f / 16.0f));   // TAU = 16
        e = g_val[n] ? e : 0.f;
        den += e;
        if (g_lab[n] == labq) num += e;
    }
    s_den[tid] = den; s_num[tid] = num;
    __syncthreads();
    for (int w = 64; w > 0; w >>= 1) {
        if (tid < w) { s_den[tid] += s_den[tid + w]; s_num[tid] += s_num[tid + w]; }
        __syncthreads();
    }
    if (tid == 0)
        g_per[q] = g_val[q] ? -logf(s_num[0] / s_den[0]) : 0.f;
}

// ---------------- 6: final scalar ----------------
__global__ void k_final(const float* __restrict__ t_logit,
                        const float* __restrict__ ori,
                        const float* __restrict__ l2w,
                        float* __restrict__ out) {
    __shared__ float s_c[16];
    int tid = threadIdx.x;
    if (tid < 16) {
        float s = 0.f; int c = 0;
        for (int k = 0; k < KH; k++) { int r = tid * KH + k; s += g_per[r]; c += g_val[r]; }
        for (int k = 0; k < KL; k++) { int r = HROWS + tid * KL + k; s += g_per[r]; c += g_val[r]; }
        s_c[tid] = s / (float)c;
    }
    __syncthreads();
    if (tid == 0) {
        float contr = 0.f;
        for (int b = 0; b < B_; b++) contr += s_c[b];
        contr /= (float)B_;

        float t = t_logit[0];
        float ce = 0.f;
        for (int b = 0; b < B_; b++) {
            float se = expf(ori[b * 2 + 0]) + expf(ori[b * 2 + 1]);
            ce += -logf(expf(t) / se);
        }
        ce /= (float)B_;

        float gmax = __uint_as_float(g_max_bits);
        float meanv = g_sum / (float)(B_ * N_);
        float Dm = meanv / gmax;
        float l2 = 0.0001f * (1.f - Dm) * (1.f - Dm) * l2w[0];

        out[0] = contr + ce + l2;
    }
}

// ---------------- launch ----------------
extern "C" void kernel_launch(void* const* d_in, const int* in_sizes, int n_in,
                              void* d_out, int out_size) {
    const float* fea     = (const float*)d_in[0];
    const float* score   = (const float*)d_in[1];
    const int*   label   = (const int*)d_in[2];
    const float* t_logit = (const float*)d_in[3];
    const float* ori     = (const float*)d_in[4];
    const float* l2w     = (const float*)d_in[5];
    float* out = (float*)d_out;

    k_init<<<1, 32>>>();
    k_reduce<<<32, 256>>>(score);
    k_select<<<B_, 256>>>(score, label);
    k_gather<<<ROWS, 256>>>(fea);
    k_gemm<<<dim3(ROWS / BM, ROWS / BN, SPLITK), 256>>>();
    k_rowloss<<<ROWS, 128>>>();
    k_final<<<1, 32>>>(t_logit, ori, l2w, out);
}